// round 6
// baseline (speedup 1.0000x reference)
#include <cuda_runtime.h>
#include <cuda_bf16.h>
#include <cstdint>

// Problem dims (fixed by the dataset)
#define B_ROWS 65536
#define F_DIM  256
#define U_DIM  1024

// GEMM tiling: 128x128 CTA tile, 512 threads, 4x4 warps of 32x32
#define BM 128
#define BN 128
#define BK 64                     // 64 bf16 = 128B row (swizzle atom)
#define KITERS (F_DIM / BK)       // 4
#define NTHREADS 512
#define STAGES 3

#define A_STG_BYTES 16384                    // 128*64*2
#define STG_BYTES   32768                    // A + B
#define SMEM_BYTES  (STAGES * STG_BYTES)     // 96KB -> 2 CTAs/SM

// device-global scratch (allocations are forbidden)
__device__ __nv_bfloat16 g_xb[(size_t)B_ROWS * F_DIM];  // x in bf16 [B,F]
__device__ __nv_bfloat16 g_wt[(size_t)U_DIM * F_DIM];   // w transposed bf16 [U,F]
__device__ float g_wsq[U_DIM];
__device__ float g_xsq[B_ROWS];

// ---------------- PTX helpers ----------------
__device__ __forceinline__ uint32_t smem_u32(const void* p) {
    uint32_t a;
    asm("{ .reg .u64 t; cvta.to.shared.u64 t, %1; cvt.u32.u64 %0, t; }" : "=r"(a) : "l"(p));
    return a;
}
__device__ __forceinline__ void cp_async16(uint32_t dst, const void* src) {
    asm volatile("cp.async.cg.shared.global [%0], [%1], 16;" :: "r"(dst), "l"(src));
}
__device__ __forceinline__ void cp_commit() {
    asm volatile("cp.async.commit_group;" ::: "memory");
}
template<int N>
__device__ __forceinline__ void cp_wait() {
    asm volatile("cp.async.wait_group %0;" :: "n"(N) : "memory");
}
__device__ __forceinline__ void ldmatrix_x4(uint32_t* r, uint32_t addr) {
    asm volatile("ldmatrix.sync.aligned.m8n8.x4.shared.b16 {%0,%1,%2,%3}, [%4];"
                 : "=r"(r[0]), "=r"(r[1]), "=r"(r[2]), "=r"(r[3]) : "r"(addr));
}
__device__ __forceinline__ void mma_bf16(float* c, const uint32_t* a,
                                         uint32_t b0, uint32_t b1) {
    asm volatile(
        "mma.sync.aligned.m16n8k16.row.col.f32.bf16.bf16.f32 "
        "{%0,%1,%2,%3}, {%4,%5,%6,%7}, {%8,%9}, {%0,%1,%2,%3};"
        : "+f"(c[0]), "+f"(c[1]), "+f"(c[2]), "+f"(c[3])
        : "r"(a[0]), "r"(a[1]), "r"(a[2]), "r"(a[3]), "r"(b0), "r"(b1));
}
__device__ __forceinline__ uint32_t pack_bf16x2(float lo, float hi) {
    __nv_bfloat162 h = __floats2bfloat162_rn(lo, hi);
    return *reinterpret_cast<uint32_t*>(&h);
}

// ---------------- fused prologue (unchanged, proven) ----------------
#define XBLOCKS (B_ROWS / 8)
__global__ void __launch_bounds__(256) prep_kernel(const float* __restrict__ x,
                                                   const float* __restrict__ w) {
    int bid = blockIdx.x;
    if (bid < XBLOCKS) {
        int row = bid * 8 + (threadIdx.x >> 5);
        int lid = threadIdx.x & 31;
        const float4* xr = (const float4*)(x + (size_t)row * F_DIM);
        float4 a = xr[lid];
        float4 b = xr[lid + 32];
        float s = a.x * a.x + a.y * a.y + a.z * a.z + a.w * a.w +
                  b.x * b.x + b.y * b.y + b.z * b.z + b.w * b.w;
        #pragma unroll
        for (int o = 16; o; o >>= 1) s += __shfl_xor_sync(0xffffffffu, s, o);
        if (lid == 0) g_xsq[row] = s;

        uint32_t* dst = (uint32_t*)(g_xb + (size_t)row * F_DIM);
        dst[2 * lid + 0]  = pack_bf16x2(a.x, a.y);
        dst[2 * lid + 1]  = pack_bf16x2(a.z, a.w);
        dst[64 + 2 * lid] = pack_bf16x2(b.x, b.y);
        dst[65 + 2 * lid] = pack_bf16x2(b.z, b.w);
    } else {
        __shared__ float t[32][33];
        __shared__ float red[8][32];
        int tx = threadIdx.x & 31, ty = threadIdx.x >> 5;
        int u0 = (bid - XBLOCKS) * 32;
        float acc = 0.0f;
        #pragma unroll 1
        for (int f0 = 0; f0 < F_DIM; f0 += 32) {
            __syncthreads();
            #pragma unroll
            for (int r = 0; r < 4; ++r) {
                int f = ty + 8 * r;
                float v = w[(size_t)(f0 + f) * U_DIM + u0 + tx];
                t[f][tx] = v;
                acc += v * v;
            }
            __syncthreads();
            #pragma unroll
            for (int r = 0; r < 4; ++r) {
                int u = ty + 8 * r;
                g_wt[(size_t)(u0 + u) * F_DIM + f0 + tx] = __float2bfloat16(t[tx][u]);
            }
        }
        red[ty][tx] = acc;
        __syncthreads();
        if (ty == 0) {
            float s = 0.0f;
            #pragma unroll
            for (int r = 0; r < 8; ++r) s += red[r][tx];
            g_wsq[u0 + tx] = s;
        }
    }
}

// ---------------- main GEMM kernel ----------------
// out[m,n] = xsq[m] + wsq[n] - 2 * sum_k xb[m,k]*wt[n,k]
// Swizzle: 128B rows of 8 16B-chunks; chunk c of row r at (c ^ (r&7)).
__global__ void __launch_bounds__(NTHREADS, 2) rbf_gemm(float* __restrict__ out) {
    extern __shared__ char smem[];
    uint32_t sb = smem_u32(smem);

    int tid = threadIdx.x;
    int wid = tid >> 5, lid = tid & 31;
    int g = lid >> 2, t = lid & 3;
    int wm = wid >> 2, wn = wid & 3;          // 4 x 4 warps; warp tile 32x32
    int m0 = blockIdx.y * BM;
    int n0 = blockIdx.x * BN;

    const __nv_bfloat16* xa = g_xb + (size_t)m0 * F_DIM;
    const __nv_bfloat16* wb = g_wt + (size_t)n0 * F_DIM;

    // ldmatrix per-lane bases (byte offsets within a stage)
    // A frag i (i<2): rows wm*32 + i*16 + (lid&15); chunk-col = 2ks + (lid>>4)
    uint32_t rowoffA[2], swzA[2];
    #pragma unroll
    for (int i = 0; i < 2; ++i) {
        int r = wm * 32 + i * 16 + (lid & 15);
        rowoffA[i] = (uint32_t)r * 128;
        swzA[i] = (uint32_t)(r & 7);
    }
    // B pair jj (jj<2): n rows wn*32 + jj*16 + (lid&7) + ((lid>>4)<<3)
    uint32_t rowoffB[2], swzB[2];
    #pragma unroll
    for (int jj = 0; jj < 2; ++jj) {
        int n = wn * 32 + jj * 16 + (lid & 7) + ((lid >> 4) << 3);
        rowoffB[jj] = A_STG_BYTES + (uint32_t)n * 128;
        swzB[jj] = (uint32_t)(n & 7);
    }
    uint32_t cA_lane = (uint32_t)(lid >> 4);
    uint32_t cB_lane = (uint32_t)((lid >> 3) & 1);

    float acc[2][4][4];
    #pragma unroll
    for (int i = 0; i < 2; ++i)
        #pragma unroll
        for (int j = 0; j < 4; ++j)
            #pragma unroll
            for (int q = 0; q < 4; ++q) acc[i][j][q] = 0.0f;

    // stage loader: A 1024 chunks + B 1024 chunks, 2 each per thread
    auto load_stage = [&](int stage, int kt) {
        uint32_t abase = sb + stage * STG_BYTES;
        #pragma unroll
        for (int r = 0; r < 2; ++r) {
            int chunk = tid + r * 512;
            int row = chunk >> 3, c = chunk & 7;
            cp_async16(abase + row * 128 + ((c ^ (row & 7)) << 4),
                       xa + (size_t)row * F_DIM + kt * BK + c * 8);
        }
        uint32_t bbase = abase + A_STG_BYTES;
        #pragma unroll
        for (int r = 0; r < 2; ++r) {
            int chunk = tid + r * 512;
            int row = chunk >> 3, c = chunk & 7;
            cp_async16(bbase + row * 128 + ((c ^ (row & 7)) << 4),
                       wb + (size_t)row * F_DIM + kt * BK + c * 8);
        }
        cp_commit();
    };

    load_stage(0, 0);
    load_stage(1, 1);
    load_stage(2, 2);

    #pragma unroll
    for (int kt = 0; kt < KITERS; ++kt) {
        int s = kt % STAGES;
        cp_wait<2>();
        __syncthreads();

        uint32_t a_base = sb + s * STG_BYTES;

        #pragma unroll
        for (int ks = 0; ks < 4; ++ks) {
            uint32_t a[2][4], b[2][4];
            uint32_t cA = 2 * ks + cA_lane;
            uint32_t cB = 2 * ks + cB_lane;
            #pragma unroll
            for (int i = 0; i < 2; ++i)
                ldmatrix_x4(a[i], a_base + rowoffA[i] + ((cA ^ swzA[i]) << 4));
            #pragma unroll
            for (int jj = 0; jj < 2; ++jj)
                ldmatrix_x4(b[jj], a_base + rowoffB[jj] + ((cB ^ swzB[jj]) << 4));
            #pragma unroll
            for (int i = 0; i < 2; ++i)
                #pragma unroll
                for (int jj = 0; jj < 2; ++jj) {
                    mma_bf16(acc[i][2 * jj + 0], a[i], b[jj][0], b[jj][1]);
                    mma_bf16(acc[i][2 * jj + 1], a[i], b[jj][2], b[jj][3]);
                }
        }
        __syncthreads();
        if (kt + STAGES < KITERS) load_stage(s, kt + STAGES);
        else cp_commit();  // empty group keeps wait<2> uniform
    }

    // fused epilogue: out = xsq + wsq - 2*cross (float2 stores)
    #pragma unroll
    for (int i = 0; i < 2; ++i) {
        int mlo = m0 + wm * 32 + i * 16 + g;
        int mhi = mlo + 8;
        float xlo = g_xsq[mlo];
        float xhi = g_xsq[mhi];
        #pragma unroll
        for (int j = 0; j < 4; ++j) {
            int n = n0 + wn * 32 + j * 8 + 2 * t;
            float2 ws = *(const float2*)(g_wsq + n);
            float2 olo, ohi;
            olo.x = fmaf(-2.0f, acc[i][j][0], xlo + ws.x);
            olo.y = fmaf(-2.0f, acc[i][j][1], xlo + ws.y);
            ohi.x = fmaf(-2.0f, acc[i][j][2], xhi + ws.x);
            ohi.y = fmaf(-2.0f, acc[i][j][3], xhi + ws.y);
            *(float2*)(out + (size_t)mlo * U_DIM + n) = olo;
            *(float2*)(out + (size_t)mhi * U_DIM + n) = ohi;
        }
    }
}

// ---------------- host launch ----------------
extern "C" void kernel_launch(void* const* d_in, const int* in_sizes, int n_in,
                              void* d_out, int out_size) {
    const float* x = (const float*)d_in[0];
    const float* w = (const float*)d_in[1];
    float* out = (float*)d_out;

    prep_kernel<<<XBLOCKS + U_DIM / 32, 256>>>(x, w);

    cudaFuncSetAttribute(rbf_gemm, cudaFuncAttributeMaxDynamicSharedMemorySize, SMEM_BYTES);
    dim3 grid(U_DIM / BN, B_ROWS / BM);  // (8, 512): n-tiles adjacent -> A reuse in L2
    rbf_gemm<<<grid, NTHREADS, SMEM_BYTES>>>(out);
}

// round 7
// speedup vs baseline: 1.0661x; 1.0661x over previous
#include <cuda_runtime.h>
#include <cuda_bf16.h>
#include <cstdint>

// Problem dims (fixed by the dataset)
#define B_ROWS 65536
#define F_DIM  256
#define U_DIM  1024

// CTA 128x128, 128 threads (4 warps, 2x2 grid of 64x64 warp tiles)
#define BM 128
#define BN 128
#define BK 64                     // 64 bf16 = 128B row (swizzle atom)
#define KITERS (F_DIM / BK)       // 4
#define NTHREADS 128
#define STAGES 3

#define A_STG_BYTES 16384                    // 128*64*2
#define STG_BYTES   32768                    // A + B
#define SMEM_BYTES  (STAGES * STG_BYTES)     // 96KB -> 2 CTAs/SM

// device-global scratch (allocations are forbidden)
__device__ __nv_bfloat16 g_xb[(size_t)B_ROWS * F_DIM];  // x in bf16 [B,F]
__device__ __nv_bfloat16 g_wt[(size_t)U_DIM * F_DIM];   // w transposed bf16 [U,F]
__device__ float g_wsq[U_DIM];
__device__ float g_xsq[B_ROWS];

// ---------------- PTX helpers ----------------
__device__ __forceinline__ uint32_t smem_u32(const void* p) {
    uint32_t a;
    asm("{ .reg .u64 t; cvta.to.shared.u64 t, %1; cvt.u32.u64 %0, t; }" : "=r"(a) : "l"(p));
    return a;
}
__device__ __forceinline__ void cp_async16(uint32_t dst, const void* src) {
    asm volatile("cp.async.cg.shared.global [%0], [%1], 16;" :: "r"(dst), "l"(src));
}
__device__ __forceinline__ void cp_commit() {
    asm volatile("cp.async.commit_group;" ::: "memory");
}
template<int N>
__device__ __forceinline__ void cp_wait() {
    asm volatile("cp.async.wait_group %0;" :: "n"(N) : "memory");
}
__device__ __forceinline__ void ldmatrix_x4(uint32_t* r, uint32_t addr) {
    asm volatile("ldmatrix.sync.aligned.m8n8.x4.shared.b16 {%0,%1,%2,%3}, [%4];"
                 : "=r"(r[0]), "=r"(r[1]), "=r"(r[2]), "=r"(r[3]) : "r"(addr));
}
__device__ __forceinline__ void mma_bf16(float* c, const uint32_t* a,
                                         uint32_t b0, uint32_t b1) {
    asm volatile(
        "mma.sync.aligned.m16n8k16.row.col.f32.bf16.bf16.f32 "
        "{%0,%1,%2,%3}, {%4,%5,%6,%7}, {%8,%9}, {%0,%1,%2,%3};"
        : "+f"(c[0]), "+f"(c[1]), "+f"(c[2]), "+f"(c[3])
        : "r"(a[0]), "r"(a[1]), "r"(a[2]), "r"(a[3]), "r"(b0), "r"(b1));
}
__device__ __forceinline__ uint32_t pack_bf16x2(float lo, float hi) {
    __nv_bfloat162 h = __floats2bfloat162_rn(lo, hi);
    return *reinterpret_cast<uint32_t*>(&h);
}

// ---------------- fused prologue (unchanged, proven) ----------------
#define XBLOCKS (B_ROWS / 8)
__global__ void __launch_bounds__(256) prep_kernel(const float* __restrict__ x,
                                                   const float* __restrict__ w) {
    int bid = blockIdx.x;
    if (bid < XBLOCKS) {
        int row = bid * 8 + (threadIdx.x >> 5);
        int lid = threadIdx.x & 31;
        const float4* xr = (const float4*)(x + (size_t)row * F_DIM);
        float4 a = xr[lid];
        float4 b = xr[lid + 32];
        float s = a.x * a.x + a.y * a.y + a.z * a.z + a.w * a.w +
                  b.x * b.x + b.y * b.y + b.z * b.z + b.w * b.w;
        #pragma unroll
        for (int o = 16; o; o >>= 1) s += __shfl_xor_sync(0xffffffffu, s, o);
        if (lid == 0) g_xsq[row] = s;

        uint32_t* dst = (uint32_t*)(g_xb + (size_t)row * F_DIM);
        dst[2 * lid + 0]  = pack_bf16x2(a.x, a.y);
        dst[2 * lid + 1]  = pack_bf16x2(a.z, a.w);
        dst[64 + 2 * lid] = pack_bf16x2(b.x, b.y);
        dst[65 + 2 * lid] = pack_bf16x2(b.z, b.w);
    } else {
        __shared__ float t[32][33];
        __shared__ float red[8][32];
        int tx = threadIdx.x & 31, ty = threadIdx.x >> 5;
        int u0 = (bid - XBLOCKS) * 32;
        float acc = 0.0f;
        #pragma unroll 1
        for (int f0 = 0; f0 < F_DIM; f0 += 32) {
            __syncthreads();
            #pragma unroll
            for (int r = 0; r < 4; ++r) {
                int f = ty + 8 * r;
                float v = w[(size_t)(f0 + f) * U_DIM + u0 + tx];
                t[f][tx] = v;
                acc += v * v;
            }
            __syncthreads();
            #pragma unroll
            for (int r = 0; r < 4; ++r) {
                int u = ty + 8 * r;
                g_wt[(size_t)(u0 + u) * F_DIM + f0 + tx] = __float2bfloat16(t[tx][u]);
            }
        }
        red[ty][tx] = acc;
        __syncthreads();
        if (ty == 0) {
            float s = 0.0f;
            #pragma unroll
            for (int r = 0; r < 8; ++r) s += red[r][tx];
            g_wsq[u0 + tx] = s;
        }
    }
}

// ---------------- main GEMM kernel ----------------
// out[m,n] = xsq[m] + wsq[n] - 2 * sum_k xb[m,k]*wt[n,k]
// Swizzle: 128B rows of 8 16B-chunks; chunk c of row r at (c ^ (r&7)).
__global__ void __launch_bounds__(NTHREADS, 2) rbf_gemm(float* __restrict__ out) {
    extern __shared__ char smem[];
    uint32_t sb = smem_u32(smem);

    int tid = threadIdx.x;
    int wid = tid >> 5, lid = tid & 31;
    int g = lid >> 2, t = lid & 3;
    int wm = wid >> 1, wn = wid & 1;          // 2 x 2 warps; warp tile 64x64
    int m0 = blockIdx.y * BM;
    int n0 = blockIdx.x * BN;

    const __nv_bfloat16* xa = g_xb + (size_t)m0 * F_DIM;
    const __nv_bfloat16* wb = g_wt + (size_t)n0 * F_DIM;

    // ldmatrix per-lane bases (byte offsets within a stage)
    uint32_t rowoffA[4], swzA[4];
    #pragma unroll
    for (int i = 0; i < 4; ++i) {
        int r = wm * 64 + i * 16 + (lid & 15);
        rowoffA[i] = (uint32_t)r * 128;
        swzA[i] = (uint32_t)(r & 7);
    }
    uint32_t rowoffB[4], swzB[4];
    #pragma unroll
    for (int jj = 0; jj < 4; ++jj) {
        int n = wn * 64 + jj * 16 + (lid & 7) + ((lid >> 4) << 3);
        rowoffB[jj] = A_STG_BYTES + (uint32_t)n * 128;
        swzB[jj] = (uint32_t)(n & 7);
    }
    uint32_t cA_lane = (uint32_t)(lid >> 4);
    uint32_t cB_lane = (uint32_t)((lid >> 3) & 1);

    // loader chunk geometry (same for A and B): 1024 chunks each, 8/thread
    uint32_t ld_soff[8];   // swizzled smem offset within a 16KB block
    uint32_t ld_goff[8];   // gmem element offset (row*F_DIM + c*8), sans kt
    #pragma unroll
    for (int r = 0; r < 8; ++r) {
        int chunk = tid + r * 128;
        int row = chunk >> 3, c = chunk & 7;
        ld_soff[r] = (uint32_t)(row * 128 + ((c ^ (row & 7)) << 4));
        ld_goff[r] = (uint32_t)(row * F_DIM + c * 8);
    }

    float acc[4][8][4];
    #pragma unroll
    for (int i = 0; i < 4; ++i)
        #pragma unroll
        for (int j = 0; j < 8; ++j)
            #pragma unroll
            for (int q = 0; q < 4; ++q) acc[i][j][q] = 0.0f;

    // issue 2 A-chunks + 2 B-chunks (quarter of a stage)
    auto load_quarter = [&](uint32_t lbase, int lkt, int q) {
        #pragma unroll
        for (int r = 2 * q; r < 2 * q + 2; ++r) {
            cp_async16(lbase + ld_soff[r], xa + (size_t)lkt * BK + ld_goff[r]);
            cp_async16(lbase + A_STG_BYTES + ld_soff[r],
                       wb + (size_t)lkt * BK + ld_goff[r]);
        }
    };

    // prologue: stages 0 and 1, one commit group each
    #pragma unroll
    for (int q = 0; q < 4; ++q) load_quarter(sb, 0, q);
    cp_commit();
    #pragma unroll
    for (int q = 0; q < 4; ++q) load_quarter(sb + STG_BYTES, 1, q);
    cp_commit();

    uint32_t a_frag[2][4][4], b_frag[2][4][4];

    #pragma unroll
    for (int kt = 0; kt < KITERS; ++kt) {
        cp_wait<1>();
        __syncthreads();   // stage (kt-1)%3 reads done by all warps -> safe to overwrite

        uint32_t base = sb + (kt % STAGES) * STG_BYTES;
        uint32_t lbase = sb + ((kt + 2) % STAGES) * STG_BYTES;
        int lkt = kt + 2;
        bool doload = (lkt < KITERS);

        // prime fragments for ks=0
        {
            uint32_t cA = cA_lane, cB = cB_lane;
            #pragma unroll
            for (int i = 0; i < 4; ++i)
                ldmatrix_x4(a_frag[0][i], base + rowoffA[i] + ((cA ^ swzA[i]) << 4));
            #pragma unroll
            for (int jj = 0; jj < 4; ++jj)
                ldmatrix_x4(b_frag[0][jj], base + rowoffB[jj] + ((cB ^ swzB[jj]) << 4));
        }

        #pragma unroll
        for (int ks = 0; ks < 4; ++ks) {
            const int pb = ks & 1;
            if (doload) load_quarter(lbase, lkt, ks);   // spread gmem loads
            if (ks < 3) {                               // prefetch next fragments
                const int pn = (ks + 1) & 1;
                uint32_t cA = 2 * (ks + 1) + cA_lane;
                uint32_t cB = 2 * (ks + 1) + cB_lane;
                #pragma unroll
                for (int i = 0; i < 4; ++i)
                    ldmatrix_x4(a_frag[pn][i], base + rowoffA[i] + ((cA ^ swzA[i]) << 4));
                #pragma unroll
                for (int jj = 0; jj < 4; ++jj)
                    ldmatrix_x4(b_frag[pn][jj], base + rowoffB[jj] + ((cB ^ swzB[jj]) << 4));
            }
            #pragma unroll
            for (int i = 0; i < 4; ++i)
                #pragma unroll
                for (int jj = 0; jj < 4; ++jj) {
                    mma_bf16(acc[i][2 * jj + 0], a_frag[pb][i],
                             b_frag[pb][jj][0], b_frag[pb][jj][1]);
                    mma_bf16(acc[i][2 * jj + 1], a_frag[pb][i],
                             b_frag[pb][jj][2], b_frag[pb][jj][3]);
                }
        }
        cp_commit();   // one group per kt keeps wait<1> arithmetic uniform
    }

    // fused epilogue: out = xsq + wsq - 2*cross (float2 stores)
    #pragma unroll
    for (int i = 0; i < 4; ++i) {
        int mlo = m0 + wm * 64 + i * 16 + g;
        int mhi = mlo + 8;
        float xlo = g_xsq[mlo];
        float xhi = g_xsq[mhi];
        #pragma unroll
        for (int j = 0; j < 8; ++j) {
            int n = n0 + wn * 64 + j * 8 + 2 * t;
            float2 ws = *(const float2*)(g_wsq + n);
            float2 olo, ohi;
            olo.x = fmaf(-2.0f, acc[i][j][0], xlo + ws.x);
            olo.y = fmaf(-2.0f, acc[i][j][1], xlo + ws.y);
            ohi.x = fmaf(-2.0f, acc[i][j][2], xhi + ws.x);
            ohi.y = fmaf(-2.0f, acc[i][j][3], xhi + ws.y);
            *(float2*)(out + (size_t)mlo * U_DIM + n) = olo;
            *(float2*)(out + (size_t)mhi * U_DIM + n) = ohi;
        }
    }
}

// ---------------- host launch ----------------
extern "C" void kernel_launch(void* const* d_in, const int* in_sizes, int n_in,
                              void* d_out, int out_size) {
    const float* x = (const float*)d_in[0];
    const float* w = (const float*)d_in[1];
    float* out = (float*)d_out;

    prep_kernel<<<XBLOCKS + U_DIM / 32, 256>>>(x, w);

    cudaFuncSetAttribute(rbf_gemm, cudaFuncAttributeMaxDynamicSharedMemorySize, SMEM_BYTES);
    dim3 grid(U_DIM / BN, B_ROWS / BM);  // (8, 512): n-tiles adjacent -> A reuse in L2
    rbf_gemm<<<grid, NTHREADS, SMEM_BYTES>>>(out);
}

// round 8
// speedup vs baseline: 1.0804x; 1.0134x over previous
#include <cuda_runtime.h>
#include <cuda_fp16.h>
#include <cstdint>

// Problem dims (fixed by the dataset)
#define B_ROWS 65536
#define F_DIM  256
#define U_DIM  1024

// GEMM tiling — R4's proven shape (best so far): 128x128 CTA, 2x4 warps of 64x32
#define BM 128
#define BN 128
#define BK 64                     // 64 fp16 = 128B row (swizzle atom)
#define KITERS (F_DIM / BK)       // 4
#define NTHREADS 256
#define STAGES 3

#define A_STG_BYTES 16384                    // 128*64*2
#define STG_BYTES   32768                    // A + B
#define SMEM_BYTES  (STAGES * STG_BYTES)     // 96KB -> 2 CTAs/SM

// device-global scratch (allocations are forbidden)
__device__ __half g_xb[(size_t)B_ROWS * F_DIM];  // x in fp16 [B,F]
__device__ __half g_wt[(size_t)U_DIM * F_DIM];   // w transposed fp16 [U,F]
__device__ float g_wsq[U_DIM];
__device__ float g_xsq[B_ROWS];

// ---------------- PTX helpers ----------------
__device__ __forceinline__ uint32_t smem_u32(const void* p) {
    uint32_t a;
    asm("{ .reg .u64 t; cvta.to.shared.u64 t, %1; cvt.u32.u64 %0, t; }" : "=r"(a) : "l"(p));
    return a;
}
__device__ __forceinline__ void cp_async16(uint32_t dst, const void* src) {
    asm volatile("cp.async.cg.shared.global [%0], [%1], 16;" :: "r"(dst), "l"(src));
}
__device__ __forceinline__ void cp_commit() {
    asm volatile("cp.async.commit_group;" ::: "memory");
}
template<int N>
__device__ __forceinline__ void cp_wait() {
    asm volatile("cp.async.wait_group %0;" :: "n"(N) : "memory");
}
__device__ __forceinline__ void ldmatrix_x4(uint32_t* r, uint32_t addr) {
    asm volatile("ldmatrix.sync.aligned.m8n8.x4.shared.b16 {%0,%1,%2,%3}, [%4];"
                 : "=r"(r[0]), "=r"(r[1]), "=r"(r[2]), "=r"(r[3]) : "r"(addr));
}
// fp16 inputs, fp16 accumulators (the potentially double-rate variant)
__device__ __forceinline__ void mma_f16acc(uint32_t* c, const uint32_t* a,
                                           uint32_t b0, uint32_t b1) {
    asm volatile(
        "mma.sync.aligned.m16n8k16.row.col.f16.f16.f16.f16 "
        "{%0,%1}, {%2,%3,%4,%5}, {%6,%7}, {%0,%1};"
        : "+r"(c[0]), "+r"(c[1])
        : "r"(a[0]), "r"(a[1]), "r"(a[2]), "r"(a[3]), "r"(b0), "r"(b1));
}
__device__ __forceinline__ uint32_t pack_h16x2(float lo, float hi) {
    __half2 h = __floats2half2_rn(lo, hi);
    return *reinterpret_cast<uint32_t*>(&h);
}

// ---------------- fused prologue ----------------
#define XBLOCKS (B_ROWS / 8)
__global__ void __launch_bounds__(256) prep_kernel(const float* __restrict__ x,
                                                   const float* __restrict__ w) {
    int bid = blockIdx.x;
    if (bid < XBLOCKS) {
        int row = bid * 8 + (threadIdx.x >> 5);
        int lid = threadIdx.x & 31;
        const float4* xr = (const float4*)(x + (size_t)row * F_DIM);
        float4 a = xr[lid];
        float4 b = xr[lid + 32];
        float s = a.x * a.x + a.y * a.y + a.z * a.z + a.w * a.w +
                  b.x * b.x + b.y * b.y + b.z * b.z + b.w * b.w;
        #pragma unroll
        for (int o = 16; o; o >>= 1) s += __shfl_xor_sync(0xffffffffu, s, o);
        if (lid == 0) g_xsq[row] = s;

        uint32_t* dst = (uint32_t*)(g_xb + (size_t)row * F_DIM);
        dst[2 * lid + 0]  = pack_h16x2(a.x, a.y);
        dst[2 * lid + 1]  = pack_h16x2(a.z, a.w);
        dst[64 + 2 * lid] = pack_h16x2(b.x, b.y);
        dst[65 + 2 * lid] = pack_h16x2(b.z, b.w);
    } else {
        __shared__ float t[32][33];
        __shared__ float red[8][32];
        int tx = threadIdx.x & 31, ty = threadIdx.x >> 5;
        int u0 = (bid - XBLOCKS) * 32;
        float acc = 0.0f;
        #pragma unroll 1
        for (int f0 = 0; f0 < F_DIM; f0 += 32) {
            __syncthreads();
            #pragma unroll
            for (int r = 0; r < 4; ++r) {
                int f = ty + 8 * r;
                float v = w[(size_t)(f0 + f) * U_DIM + u0 + tx];
                t[f][tx] = v;
                acc += v * v;
            }
            __syncthreads();
            #pragma unroll
            for (int r = 0; r < 4; ++r) {
                int u = ty + 8 * r;
                g_wt[(size_t)(u0 + u) * F_DIM + f0 + tx] = __float2half(t[tx][u]);
            }
        }
        red[ty][tx] = acc;
        __syncthreads();
        if (ty == 0) {
            float s = 0.0f;
            #pragma unroll
            for (int r = 0; r < 8; ++r) s += red[r][tx];
            g_wsq[u0 + tx] = s;
        }
    }
}

// ---------------- main GEMM kernel ----------------
// out[m,n] = xsq[m] + wsq[n] - 2 * sum_k xb[m,k]*wt[n,k]
// fp16 accumulation in two banks (even/odd kt), combined in fp32 at epilogue.
// Swizzle: 128B rows of 8 16B-chunks; chunk c of row r at (c ^ (r&7)).
__global__ void __launch_bounds__(NTHREADS, 2) rbf_gemm(float* __restrict__ out) {
    extern __shared__ char smem[];
    uint32_t sb = smem_u32(smem);

    int tid = threadIdx.x;
    int wid = tid >> 5, lid = tid & 31;
    int g = lid >> 2, t = lid & 3;
    int wm = wid >> 2, wn = wid & 3;          // 2 x 4 warps; warp tile 64x32
    int m0 = blockIdx.y * BM;
    int n0 = blockIdx.x * BN;

    const __half* xa = g_xb + (size_t)m0 * F_DIM;
    const __half* wb = g_wt + (size_t)n0 * F_DIM;

    // ldmatrix per-lane bases (byte offsets within a stage)
    uint32_t rowoffA[4], swzA[4];
    #pragma unroll
    for (int i = 0; i < 4; ++i) {
        int r = wm * 64 + i * 16 + (lid & 15);
        rowoffA[i] = (uint32_t)r * 128;
        swzA[i] = (uint32_t)(r & 7);
    }
    uint32_t rowoffB[2], swzB[2];
    #pragma unroll
    for (int jj = 0; jj < 2; ++jj) {
        int n = wn * 32 + jj * 16 + (lid & 7) + ((lid >> 4) << 3);
        rowoffB[jj] = A_STG_BYTES + (uint32_t)n * 128;
        swzB[jj] = (uint32_t)(n & 7);
    }
    uint32_t cA_lane = (uint32_t)(lid >> 4);
    uint32_t cB_lane = (uint32_t)((lid >> 3) & 1);

    // two fp16 accumulator banks: [bank][i][j][2 x f16x2 regs]
    uint32_t acc[2][4][4][2];
    #pragma unroll
    for (int bk = 0; bk < 2; ++bk)
        #pragma unroll
        for (int i = 0; i < 4; ++i)
            #pragma unroll
            for (int j = 0; j < 4; ++j) {
                acc[bk][i][j][0] = 0u;
                acc[bk][i][j][1] = 0u;
            }

    // stage loader: A 1024 chunks + B 1024 chunks, 4 each per thread
    auto load_stage = [&](int stage, int kt) {
        uint32_t abase = sb + stage * STG_BYTES;
        #pragma unroll
        for (int r = 0; r < 4; ++r) {
            int chunk = tid + r * 256;
            int row = chunk >> 3, c = chunk & 7;
            cp_async16(abase + row * 128 + ((c ^ (row & 7)) << 4),
                       xa + (size_t)row * F_DIM + kt * BK + c * 8);
        }
        uint32_t bbase = abase + A_STG_BYTES;
        #pragma unroll
        for (int r = 0; r < 4; ++r) {
            int chunk = tid + r * 256;
            int row = chunk >> 3, c = chunk & 7;
            cp_async16(bbase + row * 128 + ((c ^ (row & 7)) << 4),
                       wb + (size_t)row * F_DIM + kt * BK + c * 8);
        }
        cp_commit();
    };

    load_stage(0, 0);
    load_stage(1, 1);
    load_stage(2, 2);

    #pragma unroll
    for (int kt = 0; kt < KITERS; ++kt) {
        int s = kt % STAGES;
        int bk = kt & 1;
        cp_wait<2>();
        __syncthreads();

        uint32_t a_base = sb + s * STG_BYTES;

        #pragma unroll
        for (int ks = 0; ks < 4; ++ks) {
            uint32_t a[4][4], b[2][4];
            uint32_t cA = 2 * ks + cA_lane;
            uint32_t cB = 2 * ks + cB_lane;
            #pragma unroll
            for (int i = 0; i < 4; ++i)
                ldmatrix_x4(a[i], a_base + rowoffA[i] + ((cA ^ swzA[i]) << 4));
            #pragma unroll
            for (int jj = 0; jj < 2; ++jj)
                ldmatrix_x4(b[jj], a_base + rowoffB[jj] + ((cB ^ swzB[jj]) << 4));
            #pragma unroll
            for (int i = 0; i < 4; ++i)
                #pragma unroll
                for (int jj = 0; jj < 2; ++jj) {
                    mma_f16acc(acc[bk][i][2 * jj + 0], a[i], b[jj][0], b[jj][1]);
                    mma_f16acc(acc[bk][i][2 * jj + 1], a[i], b[jj][2], b[jj][3]);
                }
        }
        __syncthreads();
        if (kt + STAGES < KITERS) load_stage(s, kt + STAGES);
        else cp_commit();  // empty group keeps wait<2> uniform
    }

    // fused epilogue: combine banks in fp32; out = xsq + wsq - 2*cross
    #pragma unroll
    for (int i = 0; i < 4; ++i) {
        int mlo = m0 + wm * 64 + i * 16 + g;
        int mhi = mlo + 8;
        float xlo = g_xsq[mlo];
        float xhi = g_xsq[mhi];
        #pragma unroll
        for (int j = 0; j < 4; ++j) {
            int n = n0 + wn * 32 + j * 8 + 2 * t;
            float2 ws = *(const float2*)(g_wsq + n);
            // reg 0 holds (row g, cols 2t, 2t+1); reg 1 holds (row g+8, same cols)
            float2 p0 = __half22float2(*(__half2*)&acc[0][i][j][0]);
            float2 q0 = __half22float2(*(__half2*)&acc[1][i][j][0]);
            float2 p1 = __half22float2(*(__half2*)&acc[0][i][j][1]);
            float2 q1 = __half22float2(*(__half2*)&acc[1][i][j][1]);
            float2 olo, ohi;
            olo.x = fmaf(-2.0f, p0.x + q0.x, xlo + ws.x);
            olo.y = fmaf(-2.0f, p0.y + q0.y, xlo + ws.y);
            ohi.x = fmaf(-2.0f, p1.x + q1.x, xhi + ws.x);
            ohi.y = fmaf(-2.0f, p1.y + q1.y, xhi + ws.y);
            *(float2*)(out + (size_t)mlo * U_DIM + n) = olo;
            *(float2*)(out + (size_t)mhi * U_DIM + n) = ohi;
        }
    }
}

// ---------------- host launch ----------------
extern "C" void kernel_launch(void* const* d_in, const int* in_sizes, int n_in,
                              void* d_out, int out_size) {
    const float* x = (const float*)d_in[0];
    const float* w = (const float*)d_in[1];
    float* out = (float*)d_out;

    prep_kernel<<<XBLOCKS + U_DIM / 32, 256>>>(x, w);

    cudaFuncSetAttribute(rbf_gemm, cudaFuncAttributeMaxDynamicSharedMemorySize, SMEM_BYTES);
    dim3 grid(U_DIM / BN, B_ROWS / BM);  // (8, 512): n-tiles adjacent -> A reuse in L2
    rbf_gemm<<<grid, NTHREADS, SMEM_BYTES>>>(out);
}